// round 4
// baseline (speedup 1.0000x reference)
#include <cuda_runtime.h>
#include <cstdint>

#define NB 4
#define NL 2048
#define ND 1024
#define NH 16
#define NDH 64
#define NM (NB*NL)

// Scratch (allocation-free rule: __device__ globals)
static __device__ float g_q[(size_t)NB*NH*NL*NDH];
static __device__ float g_k[(size_t)NB*NH*NL*NDH];
static __device__ float g_v[(size_t)NB*NH*NL*NDH];
static __device__ float g_att[(size_t)NM*ND];

__device__ __forceinline__ uint32_t f2tf(float x){
    uint32_t u; asm("cvt.rna.tf32.f32 %0, %1;" : "=r"(u) : "f"(x)); return u;
}
__device__ __forceinline__ float tfb(float x){ return __uint_as_float(f2tf(x)); }
__device__ __forceinline__ float4 tf4(float4 v){
    v.x = tfb(v.x); v.y = tfb(v.y); v.z = tfb(v.z); v.w = tfb(v.w); return v;
}

__device__ __forceinline__ void mma8(float* c,
    uint32_t a0, uint32_t a1, uint32_t a2, uint32_t a3,
    uint32_t b0, uint32_t b1)
{
    asm volatile(
      "mma.sync.aligned.m16n8k8.row.col.f32.tf32.tf32.f32 "
      "{%0,%1,%2,%3},{%4,%5,%6,%7},{%8,%9},{%0,%1,%2,%3};"
      : "+f"(c[0]), "+f"(c[1]), "+f"(c[2]), "+f"(c[3])
      : "r"(a0), "r"(a1), "r"(a2), "r"(a3), "r"(b0), "r"(b1));
}

// ---------------------------------------------------------------------------
// GEMM: C[M,N] = A[M,K] @ W[K,N] + bias, M=8192, K=N=1024, tf32 MMA.
// Block 128x128x32, 8 warps in 2x4 grid, warp tile 64x32 (4x4 m16n8 tiles).
// QKV=true: blockIdx.z in {0,1,2} selects (Wq,bq)->g_q etc., and the
// epilogue permutes to [B,H,L,Dh]. QKV=false: plain row-major, single W.
// ---------------------------------------------------------------------------
constexpr int AS_STRIDE = 36;    // 32 + 4 pad
constexpr int BS_STRIDE = 136;   // 128 + 8 pad
constexpr int AS_SZ = 128*AS_STRIDE;
constexpr int BS_SZ = 32*BS_STRIDE;
constexpr int GEMM_SMEM = (2*AS_SZ + 2*BS_SZ)*4;   // 71680 B

template<bool QKV>
__global__ void __launch_bounds__(256) gemm_tf32_kernel(
    const float* __restrict__ A,
    const float* __restrict__ W0, const float* __restrict__ b0_,
    const float* __restrict__ W1, const float* __restrict__ b1_,
    const float* __restrict__ W2, const float* __restrict__ b2_,
    float* __restrict__ C0, float* __restrict__ C1, float* __restrict__ C2)
{
    extern __shared__ float sm[];
    float* As = sm;
    float* Bs = sm + 2*AS_SZ;

    const float* W;  const float* bias;  float* C;
    if (QKV){
        const int z = blockIdx.z;
        W    = (z == 0) ? W0 : (z == 1) ? W1 : W2;
        bias = (z == 0) ? b0_ : (z == 1) ? b1_ : b2_;
        C    = (z == 0) ? C0 : (z == 1) ? C1 : C2;
    } else {
        W = W0; bias = b0_; C = C0;
    }

    const int tid  = threadIdx.x;
    const int lane = tid & 31;
    const int warp = tid >> 5;
    const int wm   = warp >> 2;      // 0..1
    const int wn   = warp & 3;       // 0..3
    const int bm0  = blockIdx.y * 128;
    const int bn0  = blockIdx.x * 128;

    float acc[4][4][4];
    #pragma unroll
    for (int mt=0; mt<4; mt++)
      #pragma unroll
      for (int nt=0; nt<4; nt++)
        #pragma unroll
        for (int i=0; i<4; i++) acc[mt][nt][i] = 0.f;

    const int arow = tid >> 3, ac4 = (tid & 7) * 4;
    const int brow = tid >> 5, bc4 = (tid & 31) * 4;

    auto load_tiles = [&](int kt, int buf){
        #pragma unroll
        for (int p=0; p<4; p++){
            float4 v = *reinterpret_cast<const float4*>(
                A + (size_t)(bm0 + p*32 + arow)*ND + kt*32 + ac4);
            *reinterpret_cast<float4*>(
                As + buf*AS_SZ + (p*32 + arow)*AS_STRIDE + ac4) = tf4(v);
        }
        #pragma unroll
        for (int p=0; p<4; p++){
            float4 v = *reinterpret_cast<const float4*>(
                W + (size_t)(kt*32 + p*8 + brow)*ND + bn0 + bc4);
            *reinterpret_cast<float4*>(
                Bs + buf*BS_SZ + (p*8 + brow)*BS_STRIDE + bc4) = tf4(v);
        }
    };

    load_tiles(0, 0);
    __syncthreads();

    const int NKT = ND/32;   // 32
    for (int kt=0; kt<NKT; ++kt){
        const int buf = kt & 1;
        if (kt+1 < NKT) load_tiles(kt+1, buf^1);

        const float* a_ = As + buf*AS_SZ;
        const float* b_ = Bs + buf*BS_SZ;

        #pragma unroll
        for (int ks=0; ks<4; ks++){
            const int k0 = ks*8 + (lane & 3);
            uint32_t af[4][4];
            #pragma unroll
            for (int mt=0; mt<4; mt++){
                const int r0 = wm*64 + mt*16 + (lane >> 2);
                af[mt][0] = __float_as_uint(a_[ r0   *AS_STRIDE + k0    ]);
                af[mt][1] = __float_as_uint(a_[(r0+8)*AS_STRIDE + k0    ]);
                af[mt][2] = __float_as_uint(a_[ r0   *AS_STRIDE + k0 + 4]);
                af[mt][3] = __float_as_uint(a_[(r0+8)*AS_STRIDE + k0 + 4]);
            }
            #pragma unroll
            for (int nt=0; nt<4; nt++){
                const int n0 = wn*32 + nt*8 + (lane >> 2);
                uint32_t bb0 = __float_as_uint(b_[ k0   *BS_STRIDE + n0]);
                uint32_t bb1 = __float_as_uint(b_[(k0+4)*BS_STRIDE + n0]);
                #pragma unroll
                for (int mt=0; mt<4; mt++)
                    mma8(acc[mt][nt], af[mt][0],af[mt][1],af[mt][2],af[mt][3], bb0, bb1);
            }
        }
        __syncthreads();
    }

    // epilogue: bias + (optional) permute to [B,H,L,Dh]
    #pragma unroll
    for (int mt=0; mt<4; mt++){
        const int rbase = bm0 + wm*64 + mt*16 + (lane >> 2);
        #pragma unroll
        for (int nt=0; nt<4; nt++){
            const int cbase = bn0 + wn*32 + nt*8 + 2*(lane & 3);
            #pragma unroll
            for (int i=0; i<4; i++){
                const int r = rbase + (i>>1)*8;
                const int c = cbase + (i&1);
                const float v = acc[mt][nt][i] + bias[c];
                if (QKV){
                    // r = b*L + l ; c = h*Dh + dh  ->  [(b*H + h)*L + l]*Dh + dh
                    size_t idx = (((size_t)(r >> 11)*NH + (c >> 6))*NL + (r & (NL-1)))*NDH + (c & (NDH-1));
                    C[idx] = v;
                } else {
                    C[(size_t)r*ND + c] = v;
                }
            }
        }
    }
}

// ---------------------------------------------------------------------------
// FlashAttention-2, causal. BM=128 q rows per CTA, BN=64 keys per step.
// 8 warps, each owns a 16-row stripe (1 m16 tile x 8 n8 tiles).
// Q smem region reused for P. Strides chosen bank-conflict-free.
// ---------------------------------------------------------------------------
constexpr int QS = 68;   // sQ/sP stride
constexpr int KSS = 68;  // sK stride
constexpr int VSS = 72;  // sV stride
constexpr int FL_SMEM = (128*QS + 64*KSS + 64*VSS)*4;   // 70656 B

__global__ void __launch_bounds__(256) flash_kernel(
    const float* __restrict__ Qg, const float* __restrict__ Kg,
    const float* __restrict__ Vg, float* __restrict__ Og)
{
    extern __shared__ float sm[];
    float* sQ = sm;                 // [128][68], reused as sP
    float* sK = sm + 128*QS;        // [64][68]
    float* sV = sK + 64*KSS;        // [64][72]

    const int tid  = threadIdx.x;
    const int lane = tid & 31;
    const int warp = tid >> 5;
    const int bh   = blockIdx.y;            // b*H + h
    const int q0   = blockIdx.x * 128;

    const float* Qb = Qg + (size_t)bh*NL*NDH;
    const float* Kb = Kg + (size_t)bh*NL*NDH;
    const float* Vb = Vg + (size_t)bh*NL*NDH;

    // load Q tile [128,64] -> smem (tf32 bits)
    {
        const int r  = tid >> 4;            // 0..15
        const int c4 = (tid & 15) * 4;      // 0..60
        #pragma unroll
        for (int p=0; p<8; p++){
            float4 v = *reinterpret_cast<const float4*>(
                Qb + (size_t)(q0 + p*16 + r)*NDH + c4);
            *reinterpret_cast<float4*>(sQ + (p*16 + r)*QS + c4) = tf4(v);
        }
    }
    __syncthreads();

    // Q fragments to registers (warp reads only its own 16 rows)
    uint32_t qf[8][4];
    const int rloc = warp*16 + (lane >> 2);
    #pragma unroll
    for (int ks=0; ks<8; ks++){
        const int k0 = ks*8 + (lane & 3);
        qf[ks][0] = __float_as_uint(sQ[ rloc   *QS + k0    ]);
        qf[ks][1] = __float_as_uint(sQ[(rloc+8)*QS + k0    ]);
        qf[ks][2] = __float_as_uint(sQ[ rloc   *QS + k0 + 4]);
        qf[ks][3] = __float_as_uint(sQ[(rloc+8)*QS + k0 + 4]);
    }

    float o[8][4];
    #pragma unroll
    for (int nt=0; nt<8; nt++)
      #pragma unroll
      for (int i=0; i<4; i++) o[nt][i] = 0.f;

    float mi0 = -1e30f, mi1 = -1e30f, li0 = 0.f, li1 = 0.f;

    const int rg0 = q0 + rloc;
    const int ntile = (q0 + 128) >> 6;     // causal: skip everything above diag

    for (int t=0; t<ntile; ++t){
        const int kv0 = t*64;
        __syncthreads();   // prior reads of sK/sV done

        // load K,V tiles [64,64] (tf32 bits)
        {
            const int r  = tid >> 4;
            const int c4 = (tid & 15) * 4;
            #pragma unroll
            for (int p=0; p<4; p++){
                const int rr = p*16 + r;
                float4 kv = *reinterpret_cast<const float4*>(
                    Kb + (size_t)(kv0 + rr)*NDH + c4);
                *reinterpret_cast<float4*>(sK + rr*KSS + c4) = tf4(kv);
                float4 vv = *reinterpret_cast<const float4*>(
                    Vb + (size_t)(kv0 + rr)*NDH + c4);
                *reinterpret_cast<float4*>(sV + rr*VSS + c4) = tf4(vv);
            }
        }
        __syncthreads();

        // S = Q @ K^T
        float sc[8][4];
        #pragma unroll
        for (int nt=0; nt<8; nt++)
          #pragma unroll
          for (int i=0; i<4; i++) sc[nt][i] = 0.f;

        #pragma unroll
        for (int ks=0; ks<8; ks++){
            const int k0 = ks*8 + (lane & 3);
            #pragma unroll
            for (int nt=0; nt<8; nt++){
                const int n0 = nt*8 + (lane >> 2);
                uint32_t bb0 = __float_as_uint(sK[n0*KSS + k0    ]);
                uint32_t bb1 = __float_as_uint(sK[n0*KSS + k0 + 4]);
                mma8(sc[nt], qf[ks][0],qf[ks][1],qf[ks][2],qf[ks][3], bb0, bb1);
            }
        }

        // scale + causal mask
        const bool diagTile = (kv0 + 63 > q0);
        #pragma unroll
        for (int nt=0; nt<8; nt++){
            const int c0 = kv0 + nt*8 + 2*(lane & 3);
            #pragma unroll
            for (int i=0; i<4; i++){
                float s = sc[nt][i] * 0.125f;       // 1/sqrt(64)
                if (diagTile){
                    const int cc = c0 + (i & 1);
                    const int rr = rg0 + ((i >> 1) * 8);
                    if (cc > rr) s = -1e30f;
                }
                sc[nt][i] = s;
            }
        }

        // online softmax (2 rows per thread; quad lanes share rows)
        float mt0 = -1e30f, mt1 = -1e30f;
        #pragma unroll
        for (int nt=0; nt<8; nt++){
            mt0 = fmaxf(mt0, fmaxf(sc[nt][0], sc[nt][1]));
            mt1 = fmaxf(mt1, fmaxf(sc[nt][2], sc[nt][3]));
        }
        mt0 = fmaxf(mt0, __shfl_xor_sync(0xffffffffu, mt0, 1));
        mt0 = fmaxf(mt0, __shfl_xor_sync(0xffffffffu, mt0, 2));
        mt1 = fmaxf(mt1, __shfl_xor_sync(0xffffffffu, mt1, 1));
        mt1 = fmaxf(mt1, __shfl_xor_sync(0xffffffffu, mt1, 2));

        const float mn0 = fmaxf(mi0, mt0);
        const float mn1 = fmaxf(mi1, mt1);
        const float sf0 = __expf(mi0 - mn0);
        const float sf1 = __expf(mi1 - mn1);

        float sum0 = 0.f, sum1 = 0.f;
        #pragma unroll
        for (int nt=0; nt<8; nt++){
            sc[nt][0] = __expf(sc[nt][0] - mn0); sum0 += sc[nt][0];
            sc[nt][1] = __expf(sc[nt][1] - mn0); sum0 += sc[nt][1];
            sc[nt][2] = __expf(sc[nt][2] - mn1); sum1 += sc[nt][2];
            sc[nt][3] = __expf(sc[nt][3] - mn1); sum1 += sc[nt][3];
        }
        sum0 += __shfl_xor_sync(0xffffffffu, sum0, 1);
        sum0 += __shfl_xor_sync(0xffffffffu, sum0, 2);
        sum1 += __shfl_xor_sync(0xffffffffu, sum1, 1);
        sum1 += __shfl_xor_sync(0xffffffffu, sum1, 2);

        li0 = li0*sf0 + sum0;  li1 = li1*sf1 + sum1;
        mi0 = mn0;             mi1 = mn1;

        #pragma unroll
        for (int nt=0; nt<8; nt++){
            o[nt][0] *= sf0; o[nt][1] *= sf0;
            o[nt][2] *= sf1; o[nt][3] *= sf1;
        }

        // P -> smem (warp-local rows; tf32 bits)
        #pragma unroll
        for (int nt=0; nt<8; nt++){
            const int c0 = nt*8 + 2*(lane & 3);
            sQ[ rloc   *QS + c0    ] = __uint_as_float(f2tf(sc[nt][0]));
            sQ[ rloc   *QS + c0 + 1] = __uint_as_float(f2tf(sc[nt][1]));
            sQ[(rloc+8)*QS + c0    ] = __uint_as_float(f2tf(sc[nt][2]));
            sQ[(rloc+8)*QS + c0 + 1] = __uint_as_float(f2tf(sc[nt][3]));
        }
        __syncwarp();

        // O += P @ V
        #pragma unroll
        for (int ks=0; ks<8; ks++){
            const int k0 = ks*8 + (lane & 3);
            uint32_t a0 = __float_as_uint(sQ[ rloc   *QS + k0    ]);
            uint32_t a1 = __float_as_uint(sQ[(rloc+8)*QS + k0    ]);
            uint32_t a2 = __float_as_uint(sQ[ rloc   *QS + k0 + 4]);
            uint32_t a3 = __float_as_uint(sQ[(rloc+8)*QS + k0 + 4]);
            #pragma unroll
            for (int nt=0; nt<8; nt++){
                const int n0 = nt*8 + (lane >> 2);
                uint32_t bb0 = __float_as_uint(sV[ k0   *VSS + n0]);
                uint32_t bb1 = __float_as_uint(sV[(k0+4)*VSS + n0]);
                mma8(o[nt], a0, a1, a2, a3, bb0, bb1);
            }
        }
    }

    // epilogue: divide by l, store to [B,L,D]
    const float inv0 = 1.f / li0;
    const float inv1 = 1.f / li1;
    const int b = bh >> 4;    // /H
    const int h = bh & 15;
    #pragma unroll
    for (int nt=0; nt<8; nt++){
        const int d0 = nt*8 + 2*(lane & 3);
        #pragma unroll
        for (int i=0; i<4; i++){
            const int rr = rg0 + ((i >> 1) * 8);
            const int dh = d0 + (i & 1);
            const float v = o[nt][i] * ((i >= 2) ? inv1 : inv0);
            Og[((size_t)b*NL + rr)*ND + h*NDH + dh] = v;
        }
    }
}

// ---------------------------------------------------------------------------
extern "C" void kernel_launch(void* const* d_in, const int* in_sizes, int n_in,
                              void* d_out, int out_size)
{
    (void)in_sizes; (void)n_in; (void)out_size;
    const float* x  = (const float*)d_in[0];
    const float* Wq = (const float*)d_in[1];
    const float* bq = (const float*)d_in[2];
    const float* Wk = (const float*)d_in[3];
    const float* bk = (const float*)d_in[4];
    const float* Wv = (const float*)d_in[5];
    const float* bv = (const float*)d_in[6];
    const float* Wo = (const float*)d_in[7];
    const float* bo = (const float*)d_in[8];
    float* out = (float*)d_out;

    float *gq, *gk, *gv, *gatt;
    cudaGetSymbolAddress((void**)&gq,   g_q);
    cudaGetSymbolAddress((void**)&gk,   g_k);
    cudaGetSymbolAddress((void**)&gv,   g_v);
    cudaGetSymbolAddress((void**)&gatt, g_att);

    cudaFuncSetAttribute(gemm_tf32_kernel<true>,
        cudaFuncAttributeMaxDynamicSharedMemorySize, GEMM_SMEM);
    cudaFuncSetAttribute(gemm_tf32_kernel<false>,
        cudaFuncAttributeMaxDynamicSharedMemorySize, GEMM_SMEM);
    cudaFuncSetAttribute(flash_kernel,
        cudaFuncAttributeMaxDynamicSharedMemorySize, FL_SMEM);

    // fused QKV projection: z in {0,1,2}
    dim3 gqkv(ND/128, NM/128, 3);   // (8, 64, 3)
    gemm_tf32_kernel<true><<<gqkv, 256, GEMM_SMEM>>>(
        x, Wq, bq, Wk, bk, Wv, bv, gq, gk, gv);

    dim3 gf(NL/128, NB*NH);    // (16, 64)
    flash_kernel<<<gf, 256, FL_SMEM>>>(gq, gk, gv, gatt);

    dim3 gg(ND/128, NM/128);   // (8, 64)
    gemm_tf32_kernel<false><<<gg, 256, GEMM_SMEM>>>(
        gatt, Wo, bo, nullptr, nullptr, nullptr, nullptr, out, nullptr, nullptr);
}

// round 5
// speedup vs baseline: 1.0025x; 1.0025x over previous
#include <cuda_runtime.h>
#include <cstdint>

#define NB 4
#define NL 2048
#define ND 1024
#define NH 16
#define NDH 64
#define NM (NB*NL)

// Scratch (allocation-free rule: __device__ globals)
static __device__ float g_q[(size_t)NB*NH*NL*NDH];
static __device__ float g_k[(size_t)NB*NH*NL*NDH];
static __device__ float g_v[(size_t)NB*NH*NL*NDH];
static __device__ float g_att[(size_t)NM*ND];

__device__ __forceinline__ uint32_t f2tf(float x){
    uint32_t u; asm("cvt.rna.tf32.f32 %0, %1;" : "=r"(u) : "f"(x)); return u;
}
__device__ __forceinline__ float tfb(float x){ return __uint_as_float(f2tf(x)); }
__device__ __forceinline__ float4 tf4(float4 v){
    v.x = tfb(v.x); v.y = tfb(v.y); v.z = tfb(v.z); v.w = tfb(v.w); return v;
}

__device__ __forceinline__ void mma8(float* c,
    uint32_t a0, uint32_t a1, uint32_t a2, uint32_t a3,
    uint32_t b0, uint32_t b1)
{
    asm volatile(
      "mma.sync.aligned.m16n8k8.row.col.f32.tf32.tf32.f32 "
      "{%0,%1,%2,%3},{%4,%5,%6,%7},{%8,%9},{%0,%1,%2,%3};"
      : "+f"(c[0]), "+f"(c[1]), "+f"(c[2]), "+f"(c[3])
      : "r"(a0), "r"(a1), "r"(a2), "r"(a3), "r"(b0), "r"(b1));
}

// ---------------------------------------------------------------------------
// GEMM: C[M,N] = A[M,K] @ W[K,N] + bias, M=8192, K=N=1024, tf32 MMA.
// Block 128x128x32, 8 warps in 2x4 grid, warp tile 64x32 (4x4 m16n8 tiles).
// QKV=true: blockIdx.z in {0,1,2} selects (Wq,bq)->g_q etc., and the
// epilogue permutes to [B,H,L,Dh]. QKV=false: plain row-major, single W.
// ---------------------------------------------------------------------------
constexpr int AS_STRIDE = 36;    // 32 + 4 pad
constexpr int BS_STRIDE = 136;   // 128 + 8 pad
constexpr int AS_SZ = 128*AS_STRIDE;
constexpr int BS_SZ = 32*BS_STRIDE;
constexpr int GEMM_SMEM = (2*AS_SZ + 2*BS_SZ)*4;   // 71680 B

template<bool QKV>
__global__ void __launch_bounds__(256) gemm_tf32_kernel(
    const float* __restrict__ A,
    const float* __restrict__ W0, const float* __restrict__ b0_,
    const float* __restrict__ W1, const float* __restrict__ b1_,
    const float* __restrict__ W2, const float* __restrict__ b2_,
    float* __restrict__ C0, float* __restrict__ C1, float* __restrict__ C2)
{
    extern __shared__ float sm[];
    float* As = sm;
    float* Bs = sm + 2*AS_SZ;

    const float* W;  const float* bias;  float* C;
    if (QKV){
        const int z = blockIdx.z;
        W    = (z == 0) ? W0 : (z == 1) ? W1 : W2;
        bias = (z == 0) ? b0_ : (z == 1) ? b1_ : b2_;
        C    = (z == 0) ? C0 : (z == 1) ? C1 : C2;
    } else {
        W = W0; bias = b0_; C = C0;
    }

    const int tid  = threadIdx.x;
    const int lane = tid & 31;
    const int warp = tid >> 5;
    const int wm   = warp >> 2;      // 0..1
    const int wn   = warp & 3;       // 0..3
    const int bm0  = blockIdx.y * 128;
    const int bn0  = blockIdx.x * 128;

    float acc[4][4][4];
    #pragma unroll
    for (int mt=0; mt<4; mt++)
      #pragma unroll
      for (int nt=0; nt<4; nt++)
        #pragma unroll
        for (int i=0; i<4; i++) acc[mt][nt][i] = 0.f;

    const int arow = tid >> 3, ac4 = (tid & 7) * 4;
    const int brow = tid >> 5, bc4 = (tid & 31) * 4;

    auto load_tiles = [&](int kt, int buf){
        #pragma unroll
        for (int p=0; p<4; p++){
            float4 v = *reinterpret_cast<const float4*>(
                A + (size_t)(bm0 + p*32 + arow)*ND + kt*32 + ac4);
            *reinterpret_cast<float4*>(
                As + buf*AS_SZ + (p*32 + arow)*AS_STRIDE + ac4) = tf4(v);
        }
        #pragma unroll
        for (int p=0; p<4; p++){
            float4 v = *reinterpret_cast<const float4*>(
                W + (size_t)(kt*32 + p*8 + brow)*ND + bn0 + bc4);
            *reinterpret_cast<float4*>(
                Bs + buf*BS_SZ + (p*8 + brow)*BS_STRIDE + bc4) = tf4(v);
        }
    };

    load_tiles(0, 0);
    __syncthreads();

    const int NKT = ND/32;   // 32
    for (int kt=0; kt<NKT; ++kt){
        const int buf = kt & 1;
        if (kt+1 < NKT) load_tiles(kt+1, buf^1);

        const float* a_ = As + buf*AS_SZ;
        const float* b_ = Bs + buf*BS_SZ;

        #pragma unroll
        for (int ks=0; ks<4; ks++){
            const int k0 = ks*8 + (lane & 3);
            uint32_t af[4][4];
            #pragma unroll
            for (int mt=0; mt<4; mt++){
                const int r0 = wm*64 + mt*16 + (lane >> 2);
                af[mt][0] = __float_as_uint(a_[ r0   *AS_STRIDE + k0    ]);
                af[mt][1] = __float_as_uint(a_[(r0+8)*AS_STRIDE + k0    ]);
                af[mt][2] = __float_as_uint(a_[ r0   *AS_STRIDE + k0 + 4]);
                af[mt][3] = __float_as_uint(a_[(r0+8)*AS_STRIDE + k0 + 4]);
            }
            #pragma unroll
            for (int nt=0; nt<4; nt++){
                const int n0 = wn*32 + nt*8 + (lane >> 2);
                uint32_t bb0 = __float_as_uint(b_[ k0   *BS_STRIDE + n0]);
                uint32_t bb1 = __float_as_uint(b_[(k0+4)*BS_STRIDE + n0]);
                #pragma unroll
                for (int mt=0; mt<4; mt++)
                    mma8(acc[mt][nt], af[mt][0],af[mt][1],af[mt][2],af[mt][3], bb0, bb1);
            }
        }
        __syncthreads();
    }

    // epilogue: bias + (optional) permute to [B,H,L,Dh]
    #pragma unroll
    for (int mt=0; mt<4; mt++){
        const int rbase = bm0 + wm*64 + mt*16 + (lane >> 2);
        #pragma unroll
        for (int nt=0; nt<4; nt++){
            const int cbase = bn0 + wn*32 + nt*8 + 2*(lane & 3);
            #pragma unroll
            for (int i=0; i<4; i++){
                const int r = rbase + (i>>1)*8;
                const int c = cbase + (i&1);
                const float v = acc[mt][nt][i] + bias[c];
                if (QKV){
                    // r = b*L + l ; c = h*Dh + dh  ->  [(b*H + h)*L + l]*Dh + dh
                    size_t idx = (((size_t)(r >> 11)*NH + (c >> 6))*NL + (r & (NL-1)))*NDH + (c & (NDH-1));
                    C[idx] = v;
                } else {
                    C[(size_t)r*ND + c] = v;
                }
            }
        }
    }
}

// ---------------------------------------------------------------------------
// FlashAttention-2, causal. BM=128 q rows per CTA, BN=64 keys per step.
// 8 warps, each owns a 16-row stripe (1 m16 tile x 8 n8 tiles).
// Q smem region reused for P. Strides chosen bank-conflict-free.
// ---------------------------------------------------------------------------
constexpr int QS = 68;   // sQ/sP stride
constexpr int KSS = 68;  // sK stride
constexpr int VSS = 72;  // sV stride
constexpr int FL_SMEM = (128*QS + 64*KSS + 64*VSS)*4;   // 70656 B

__global__ void __launch_bounds__(256) flash_kernel(
    const float* __restrict__ Qg, const float* __restrict__ Kg,
    const float* __restrict__ Vg, float* __restrict__ Og)
{
    extern __shared__ float sm[];
    float* sQ = sm;                 // [128][68], reused as sP
    float* sK = sm + 128*QS;        // [64][68]
    float* sV = sK + 64*KSS;        // [64][72]

    const int tid  = threadIdx.x;
    const int lane = tid & 31;
    const int warp = tid >> 5;
    const int bh   = blockIdx.y;            // b*H + h
    const int q0   = blockIdx.x * 128;

    const float* Qb = Qg + (size_t)bh*NL*NDH;
    const float* Kb = Kg + (size_t)bh*NL*NDH;
    const float* Vb = Vg + (size_t)bh*NL*NDH;

    // load Q tile [128,64] -> smem (tf32 bits)
    {
        const int r  = tid >> 4;            // 0..15
        const int c4 = (tid & 15) * 4;      // 0..60
        #pragma unroll
        for (int p=0; p<8; p++){
            float4 v = *reinterpret_cast<const float4*>(
                Qb + (size_t)(q0 + p*16 + r)*NDH + c4);
            *reinterpret_cast<float4*>(sQ + (p*16 + r)*QS + c4) = tf4(v);
        }
    }
    __syncthreads();

    // Q fragments to registers (warp reads only its own 16 rows)
    uint32_t qf[8][4];
    const int rloc = warp*16 + (lane >> 2);
    #pragma unroll
    for (int ks=0; ks<8; ks++){
        const int k0 = ks*8 + (lane & 3);
        qf[ks][0] = __float_as_uint(sQ[ rloc   *QS + k0    ]);
        qf[ks][1] = __float_as_uint(sQ[(rloc+8)*QS + k0    ]);
        qf[ks][2] = __float_as_uint(sQ[ rloc   *QS + k0 + 4]);
        qf[ks][3] = __float_as_uint(sQ[(rloc+8)*QS + k0 + 4]);
    }

    float o[8][4];
    #pragma unroll
    for (int nt=0; nt<8; nt++)
      #pragma unroll
      for (int i=0; i<4; i++) o[nt][i] = 0.f;

    float mi0 = -1e30f, mi1 = -1e30f, li0 = 0.f, li1 = 0.f;

    const int rg0 = q0 + rloc;
    const int ntile = (q0 + 128) >> 6;     // causal: skip everything above diag

    for (int t=0; t<ntile; ++t){
        const int kv0 = t*64;
        __syncthreads();   // prior reads of sK/sV done

        // load K,V tiles [64,64] (tf32 bits)
        {
            const int r  = tid >> 4;
            const int c4 = (tid & 15) * 4;
            #pragma unroll
            for (int p=0; p<4; p++){
                const int rr = p*16 + r;
                float4 kv = *reinterpret_cast<const float4*>(
                    Kb + (size_t)(kv0 + rr)*NDH + c4);
                *reinterpret_cast<float4*>(sK + rr*KSS + c4) = tf4(kv);
                float4 vv = *reinterpret_cast<const float4*>(
                    Vb + (size_t)(kv0 + rr)*NDH + c4);
                *reinterpret_cast<float4*>(sV + rr*VSS + c4) = tf4(vv);
            }
        }
        __syncthreads();

        // S = Q @ K^T
        float sc[8][4];
        #pragma unroll
        for (int nt=0; nt<8; nt++)
          #pragma unroll
          for (int i=0; i<4; i++) sc[nt][i] = 0.f;

        #pragma unroll
        for (int ks=0; ks<8; ks++){
            const int k0 = ks*8 + (lane & 3);
            #pragma unroll
            for (int nt=0; nt<8; nt++){
                const int n0 = nt*8 + (lane >> 2);
                uint32_t bb0 = __float_as_uint(sK[n0*KSS + k0    ]);
                uint32_t bb1 = __float_as_uint(sK[n0*KSS + k0 + 4]);
                mma8(sc[nt], qf[ks][0],qf[ks][1],qf[ks][2],qf[ks][3], bb0, bb1);
            }
        }

        // scale + causal mask
        const bool diagTile = (kv0 + 63 > q0);
        #pragma unroll
        for (int nt=0; nt<8; nt++){
            const int c0 = kv0 + nt*8 + 2*(lane & 3);
            #pragma unroll
            for (int i=0; i<4; i++){
                float s = sc[nt][i] * 0.125f;       // 1/sqrt(64)
                if (diagTile){
                    const int cc = c0 + (i & 1);
                    const int rr = rg0 + ((i >> 1) * 8);
                    if (cc > rr) s = -1e30f;
                }
                sc[nt][i] = s;
            }
        }

        // online softmax (2 rows per thread; quad lanes share rows)
        float mt0 = -1e30f, mt1 = -1e30f;
        #pragma unroll
        for (int nt=0; nt<8; nt++){
            mt0 = fmaxf(mt0, fmaxf(sc[nt][0], sc[nt][1]));
            mt1 = fmaxf(mt1, fmaxf(sc[nt][2], sc[nt][3]));
        }
        mt0 = fmaxf(mt0, __shfl_xor_sync(0xffffffffu, mt0, 1));
        mt0 = fmaxf(mt0, __shfl_xor_sync(0xffffffffu, mt0, 2));
        mt1 = fmaxf(mt1, __shfl_xor_sync(0xffffffffu, mt1, 1));
        mt1 = fmaxf(mt1, __shfl_xor_sync(0xffffffffu, mt1, 2));

        const float mn0 = fmaxf(mi0, mt0);
        const float mn1 = fmaxf(mi1, mt1);
        const float sf0 = __expf(mi0 - mn0);
        const float sf1 = __expf(mi1 - mn1);

        float sum0 = 0.f, sum1 = 0.f;
        #pragma unroll
        for (int nt=0; nt<8; nt++){
            sc[nt][0] = __expf(sc[nt][0] - mn0); sum0 += sc[nt][0];
            sc[nt][1] = __expf(sc[nt][1] - mn0); sum0 += sc[nt][1];
            sc[nt][2] = __expf(sc[nt][2] - mn1); sum1 += sc[nt][2];
            sc[nt][3] = __expf(sc[nt][3] - mn1); sum1 += sc[nt][3];
        }
        sum0 += __shfl_xor_sync(0xffffffffu, sum0, 1);
        sum0 += __shfl_xor_sync(0xffffffffu, sum0, 2);
        sum1 += __shfl_xor_sync(0xffffffffu, sum1, 1);
        sum1 += __shfl_xor_sync(0xffffffffu, sum1, 2);

        li0 = li0*sf0 + sum0;  li1 = li1*sf1 + sum1;
        mi0 = mn0;             mi1 = mn1;

        #pragma unroll
        for (int nt=0; nt<8; nt++){
            o[nt][0] *= sf0; o[nt][1] *= sf0;
            o[nt][2] *= sf1; o[nt][3] *= sf1;
        }

        // P -> smem (warp-local rows; tf32 bits)
        #pragma unroll
        for (int nt=0; nt<8; nt++){
            const int c0 = nt*8 + 2*(lane & 3);
            sQ[ rloc   *QS + c0    ] = __uint_as_float(f2tf(sc[nt][0]));
            sQ[ rloc   *QS + c0 + 1] = __uint_as_float(f2tf(sc[nt][1]));
            sQ[(rloc+8)*QS + c0    ] = __uint_as_float(f2tf(sc[nt][2]));
            sQ[(rloc+8)*QS + c0 + 1] = __uint_as_float(f2tf(sc[nt][3]));
        }
        __syncwarp();

        // O += P @ V
        #pragma unroll
        for (int ks=0; ks<8; ks++){
            const int k0 = ks*8 + (lane & 3);
            uint32_t a0 = __float_as_uint(sQ[ rloc   *QS + k0    ]);
            uint32_t a1 = __float_as_uint(sQ[(rloc+8)*QS + k0    ]);
            uint32_t a2 = __float_as_uint(sQ[ rloc   *QS + k0 + 4]);
            uint32_t a3 = __float_as_uint(sQ[(rloc+8)*QS + k0 + 4]);
            #pragma unroll
            for (int nt=0; nt<8; nt++){
                const int n0 = nt*8 + (lane >> 2);
                uint32_t bb0 = __float_as_uint(sV[ k0   *VSS + n0]);
                uint32_t bb1 = __float_as_uint(sV[(k0+4)*VSS + n0]);
                mma8(o[nt], a0, a1, a2, a3, bb0, bb1);
            }
        }
    }

    // epilogue: divide by l, store to [B,L,D]
    const float inv0 = 1.f / li0;
    const float inv1 = 1.f / li1;
    const int b = bh >> 4;    // /H
    const int h = bh & 15;
    #pragma unroll
    for (int nt=0; nt<8; nt++){
        const int d0 = nt*8 + 2*(lane & 3);
        #pragma unroll
        for (int i=0; i<4; i++){
            const int rr = rg0 + ((i >> 1) * 8);
            const int dh = d0 + (i & 1);
            const float v = o[nt][i] * ((i >= 2) ? inv1 : inv0);
            Og[((size_t)b*NL + rr)*ND + h*NDH + dh] = v;
        }
    }
}

// ---------------------------------------------------------------------------
extern "C" void kernel_launch(void* const* d_in, const int* in_sizes, int n_in,
                              void* d_out, int out_size)
{
    (void)in_sizes; (void)n_in; (void)out_size;
    const float* x  = (const float*)d_in[0];
    const float* Wq = (const float*)d_in[1];
    const float* bq = (const float*)d_in[2];
    const float* Wk = (const float*)d_in[3];
    const float* bk = (const float*)d_in[4];
    const float* Wv = (const float*)d_in[5];
    const float* bv = (const float*)d_in[6];
    const float* Wo = (const float*)d_in[7];
    const float* bo = (const float*)d_in[8];
    float* out = (float*)d_out;

    float *gq, *gk, *gv, *gatt;
    cudaGetSymbolAddress((void**)&gq,   g_q);
    cudaGetSymbolAddress((void**)&gk,   g_k);
    cudaGetSymbolAddress((void**)&gv,   g_v);
    cudaGetSymbolAddress((void**)&gatt, g_att);

    cudaFuncSetAttribute(gemm_tf32_kernel<true>,
        cudaFuncAttributeMaxDynamicSharedMemorySize, GEMM_SMEM);
    cudaFuncSetAttribute(gemm_tf32_kernel<false>,
        cudaFuncAttributeMaxDynamicSharedMemorySize, GEMM_SMEM);
    cudaFuncSetAttribute(flash_kernel,
        cudaFuncAttributeMaxDynamicSharedMemorySize, FL_SMEM);

    // fused QKV projection: z in {0,1,2}
    dim3 gqkv(ND/128, NM/128, 3);   // (8, 64, 3)
    gemm_tf32_kernel<true><<<gqkv, 256, GEMM_SMEM>>>(
        x, Wq, bq, Wk, bk, Wv, bv, gq, gk, gv);

    dim3 gf(NL/128, NB*NH);    // (16, 64)
    flash_kernel<<<gf, 256, FL_SMEM>>>(gq, gk, gv, gatt);

    dim3 gg(ND/128, NM/128);   // (8, 64)
    gemm_tf32_kernel<false><<<gg, 256, GEMM_SMEM>>>(
        gatt, Wo, bo, nullptr, nullptr, nullptr, nullptr, out, nullptr, nullptr);
}

// round 11
// speedup vs baseline: 1.1087x; 1.1059x over previous
#include <cuda_runtime.h>
#include <cstdint>

#define NB 4
#define NL 2048
#define ND 1024
#define NH 16
#define NDH 64
#define NM (NB*NL)

// Scratch (allocation-free rule: __device__ globals)
static __device__ float g_x[(size_t)NM*ND];     // tf32-rounded x
static __device__ float g_w[(size_t)4*ND*ND];   // tf32-rounded Wq,Wk,Wv,Wo
static __device__ float g_q[(size_t)NM*ND];
static __device__ float g_k[(size_t)NM*ND];
static __device__ float g_v[(size_t)NM*ND];
static __device__ float g_att[(size_t)NM*ND];

__device__ __forceinline__ uint32_t f2tf(float x){
    uint32_t u; asm("cvt.rna.tf32.f32 %0, %1;" : "=r"(u) : "f"(x)); return u;
}
__device__ __forceinline__ float tfb(float x){ return __uint_as_float(f2tf(x)); }
__device__ __forceinline__ float4 tf4(float4 v){
    v.x = tfb(v.x); v.y = tfb(v.y); v.z = tfb(v.z); v.w = tfb(v.w); return v;
}

__device__ __forceinline__ void mma8(float* c,
    uint32_t a0, uint32_t a1, uint32_t a2, uint32_t a3,
    uint32_t b0, uint32_t b1)
{
    asm volatile(
      "mma.sync.aligned.m16n8k8.row.col.f32.tf32.tf32.f32 "
      "{%0,%1,%2,%3},{%4,%5,%6,%7},{%8,%9},{%0,%1,%2,%3};"
      : "+f"(c[0]), "+f"(c[1]), "+f"(c[2]), "+f"(c[3])
      : "r"(a0), "r"(a1), "r"(a2), "r"(a3), "r"(b0), "r"(b1));
}

__device__ __forceinline__ uint32_t smem_u32(const void* p){
    uint32_t a;
    asm("{ .reg .u64 t; cvta.to.shared.u64 t, %1; cvt.u32.u64 %0, t; }" : "=r"(a) : "l"(p));
    return a;
}
__device__ __forceinline__ void cpa16(uint32_t s, const void* g){
    asm volatile("cp.async.cg.shared.global [%0], [%1], 16;" :: "r"(s), "l"(g));
}
#define CP_COMMIT() asm volatile("cp.async.commit_group;" ::: "memory")
#define CP_WAIT0()  asm volatile("cp.async.wait_group 0;" ::: "memory")

// ---------------------------------------------------------------------------
// tf32 pre-round (grid-stride, float4)
// ---------------------------------------------------------------------------
__global__ void round_kernel(const float* __restrict__ src, float* __restrict__ dst, int n4){
    for (int i = blockIdx.x*blockDim.x + threadIdx.x; i < n4; i += gridDim.x*blockDim.x){
        float4 v = reinterpret_cast<const float4*>(src)[i];
        reinterpret_cast<float4*>(dst)[i] = tf4(v);
    }
}

// ---------------------------------------------------------------------------
// GEMM: C[8192,1024] = A @ W + bias. Block 128x128x32, 4 warps (2x1 grid of
// 64x64 warp tiles). Inputs pre-rounded tf32 -> loaders are pure cp.async,
// double-buffered. QKV: z selects bias/output, epilogue permutes to [B,H,L,Dh]
// and re-rounds (consumed by flash without conversion).
// ---------------------------------------------------------------------------
constexpr int AS_STRIDE = 36;    // 32 + 4 pad
constexpr int BS_STRIDE = 136;   // 128 + 8 pad
constexpr int AS_SZ = 128*AS_STRIDE;
constexpr int BS_SZ = 32*BS_STRIDE;
constexpr int GEMM_SMEM = (2*AS_SZ + 2*BS_SZ)*4;   // 71680 B

template<bool QKV>
__global__ void __launch_bounds__(128) gemm_kernel(
    const float* __restrict__ A, const float* __restrict__ Wall,
    const float* __restrict__ bz0, const float* __restrict__ bz1, const float* __restrict__ bz2,
    float* __restrict__ Cz0, float* __restrict__ Cz1, float* __restrict__ Cz2)
{
    extern __shared__ float sm[];
    float* As = sm;
    float* Bs = sm + 2*AS_SZ;
    const uint32_t sbase = smem_u32(sm);
    const uint32_t sbA = sbase;
    const uint32_t sbB = sbase + (uint32_t)(2*AS_SZ*4);

    const int z = QKV ? blockIdx.z : 3;
    const float* W    = Wall + (size_t)z*ND*ND;
    const float* bias = QKV ? ((z == 0) ? bz0 : (z == 1) ? bz1 : bz2) : bz0;
    float* C          = QKV ? ((z == 0) ? Cz0 : (z == 1) ? Cz1 : Cz2) : Cz0;

    const int tid  = threadIdx.x;
    const int lane = tid & 31;
    const int warp = tid >> 5;          // 0..3
    const int wm   = warp >> 1;         // 0..1
    const int wn   = warp & 1;          // 0..1
    const int bm0  = blockIdx.y * 128;
    const int bn0  = blockIdx.x * 128;

    float acc[4][8][4];
    #pragma unroll
    for (int mt=0; mt<4; mt++)
      #pragma unroll
      for (int nt=0; nt<8; nt++)
        #pragma unroll
        for (int i=0; i<4; i++) acc[mt][nt][i] = 0.f;

    const int arow = tid >> 3, ac4 = (tid & 7) * 4;     // A: 16 rows/pass x 8 chunks
    const int brow = tid >> 5, bc4 = (tid & 31) * 4;    // B: 4 rows/pass x 32 chunks

    auto load_tile = [&](int kt, int buf){
        const uint32_t sa = sbA + (uint32_t)(buf*AS_SZ*4);
        const uint32_t sb = sbB + (uint32_t)(buf*BS_SZ*4);
        #pragma unroll
        for (int p=0; p<8; p++){
            const int row = p*16 + arow;
            cpa16(sa + (uint32_t)((row*AS_STRIDE + ac4)*4),
                  A + (size_t)(bm0 + row)*ND + kt*32 + ac4);
        }
        #pragma unroll
        for (int p=0; p<8; p++){
            const int row = p*4 + brow;
            cpa16(sb + (uint32_t)((row*BS_STRIDE + bc4)*4),
                  W + (size_t)(kt*32 + row)*ND + bn0 + bc4);
        }
    };

    load_tile(0, 0); CP_COMMIT();

    const int NKT = ND/32;   // 32
    for (int kt=0; kt<NKT; ++kt){
        const int buf = kt & 1;
        CP_WAIT0();
        __syncthreads();                       // tile kt visible; prior reads of buf^1 done
        if (kt+1 < NKT){ load_tile(kt+1, buf^1); CP_COMMIT(); }

        const float* a_ = As + buf*AS_SZ;
        const float* b_ = Bs + buf*BS_SZ;

        #pragma unroll
        for (int ks=0; ks<4; ks++){
            const int k0 = ks*8 + (lane & 3);
            uint32_t af[4][4];
            #pragma unroll
            for (int mt=0; mt<4; mt++){
                const int r0 = wm*64 + mt*16 + (lane >> 2);
                af[mt][0] = __float_as_uint(a_[ r0   *AS_STRIDE + k0    ]);
                af[mt][1] = __float_as_uint(a_[(r0+8)*AS_STRIDE + k0    ]);
                af[mt][2] = __float_as_uint(a_[ r0   *AS_STRIDE + k0 + 4]);
                af[mt][3] = __float_as_uint(a_[(r0+8)*AS_STRIDE + k0 + 4]);
            }
            #pragma unroll
            for (int nt=0; nt<8; nt++){
                const int n0 = wn*64 + nt*8 + (lane >> 2);
                const uint32_t bb0 = __float_as_uint(b_[ k0   *BS_STRIDE + n0]);
                const uint32_t bb1 = __float_as_uint(b_[(k0+4)*BS_STRIDE + n0]);
                #pragma unroll
                for (int mt=0; mt<4; mt++)
                    mma8(acc[mt][nt], af[mt][0],af[mt][1],af[mt][2],af[mt][3], bb0, bb1);
            }
        }
    }

    // epilogue: bias + (QKV: permute to [B,H,L,Dh] and tf32-round)
    #pragma unroll
    for (int mt=0; mt<4; mt++){
        const int rbase = bm0 + wm*64 + mt*16 + (lane >> 2);
        #pragma unroll
        for (int nt=0; nt<8; nt++){
            const int cbase = bn0 + wn*64 + nt*8 + 2*(lane & 3);
            #pragma unroll
            for (int i=0; i<4; i++){
                const int r = rbase + (i>>1)*8;
                const int c = cbase + (i&1);
                const float v = acc[mt][nt][i] + bias[c];
                if (QKV){
                    const size_t idx = (((size_t)(r >> 11)*NH + (c >> 6))*NL + (r & (NL-1)))*NDH + (c & 63);
                    C[idx] = tfb(v);
                } else {
                    C[(size_t)r*ND + c] = v;
                }
            }
        }
    }
}

// ---------------------------------------------------------------------------
// FlashAttention-2, causal. BM=128 rows/CTA, BN=64 keys/step. 4 warps, each
// owns TWO 16-row m-tiles (32 rows) -> K/V fragment bytes per MMA halved.
// KV double-buffered via cp.async (overlaps with compute). Q region reused as P.
// Output tf32-rounded (consumed by O-proj without conversion).
// ---------------------------------------------------------------------------
constexpr int QS = 68;
constexpr int KSS = 68;
constexpr int VSS = 72;
constexpr int SK_OFF = 128*QS;                 // after sQ
constexpr int SV_OFF = SK_OFF + 2*64*KSS;      // after 2 K buffers
constexpr int FL_SMEM = (SV_OFF + 2*64*VSS)*4; // 106496 B

__global__ void __launch_bounds__(128) flash_kernel(
    const float* __restrict__ Qg, const float* __restrict__ Kg,
    const float* __restrict__ Vg, float* __restrict__ Og)
{
    extern __shared__ float sm[];
    float* sQ = sm;                                    // [128][68], reused as P
    float* sKb[2] = { sm + SK_OFF, sm + SK_OFF + 64*KSS };
    float* sVb[2] = { sm + SV_OFF, sm + SV_OFF + 64*VSS };
    const uint32_t sbase = smem_u32(sm);

    const int tid  = threadIdx.x;
    const int lane = tid & 31;
    const int warp = tid >> 5;          // 0..3
    const int bh   = blockIdx.y;
    const int q0   = blockIdx.x * 128;

    const float* Qb = Qg + (size_t)bh*NL*NDH;
    const float* Kb = Kg + (size_t)bh*NL*NDH;
    const float* Vb = Vg + (size_t)bh*NL*NDH;

    const int r_ = tid >> 4;            // 0..7
    const int c4 = (tid & 15) * 4;      // 0..60

    // Q tile [128,64] via cp.async (already tf32)
    #pragma unroll
    for (int p=0; p<16; p++){
        const int row = p*8 + r_;
        cpa16(sbase + (uint32_t)((row*QS + c4)*4), Qb + (size_t)(q0 + row)*NDH + c4);
    }
    CP_COMMIT();

    auto load_kv = [&](int t, int buf){
        const int kv0 = t*64;
        const uint32_t kb = sbase + (uint32_t)((SK_OFF + buf*64*KSS)*4);
        const uint32_t vb = sbase + (uint32_t)((SV_OFF + buf*64*VSS)*4);
        #pragma unroll
        for (int p=0; p<8; p++){
            const int row = p*8 + r_;
            cpa16(kb + (uint32_t)((row*KSS + c4)*4), Kb + (size_t)(kv0 + row)*NDH + c4);
            cpa16(vb + (uint32_t)((row*VSS + c4)*4), Vb + (size_t)(kv0 + row)*NDH + c4);
        }
    };

    CP_WAIT0();                 // Q arrived
    __syncthreads();

    // Q fragments for both m-tiles (warp's own 32 rows)
    uint32_t qf[2][8][4];
    const int rloc = warp*32 + (lane >> 2);
    #pragma unroll
    for (int mt=0; mt<2; mt++){
        const int rb = rloc + mt*16;
        #pragma unroll
        for (int ks=0; ks<8; ks++){
            const int k0 = ks*8 + (lane & 3);
            qf[mt][ks][0] = __float_as_uint(sQ[ rb   *QS + k0    ]);
            qf[mt][ks][1] = __float_as_uint(sQ[(rb+8)*QS + k0    ]);
            qf[mt][ks][2] = __float_as_uint(sQ[ rb   *QS + k0 + 4]);
            qf[mt][ks][3] = __float_as_uint(sQ[(rb+8)*QS + k0 + 4]);
        }
    }

    load_kv(0, 0); CP_COMMIT();

    float o[2][8][4];
    #pragma unroll
    for (int mt=0; mt<2; mt++)
      #pragma unroll
      for (int nt=0; nt<8; nt++)
        #pragma unroll
        for (int i=0; i<4; i++) o[mt][nt][i] = 0.f;

    float mi[2][2] = {{-1e30f,-1e30f},{-1e30f,-1e30f}};
    float li[2][2] = {{0.f,0.f},{0.f,0.f}};

    const int rg0 = q0 + rloc;
    const int ntile = q0/64 + 2;        // causal

    for (int t=0; t<ntile; ++t){
        const int kv0 = t*64;
        const int buf = t & 1;
        CP_WAIT0();
        __syncthreads();                // KV(t) visible; buf^1 reads finished everywhere
        if (t+1 < ntile){ load_kv(t+1, buf^1); CP_COMMIT(); }

        const float* K_ = sKb[buf];
        const float* V_ = sVb[buf];

        // S = Q @ K^T for both m-tiles (shared K fragments)
        float sc[2][8][4];
        #pragma unroll
        for (int mt=0; mt<2; mt++)
          #pragma unroll
          for (int nt=0; nt<8; nt++)
            #pragma unroll
            for (int i=0; i<4; i++) sc[mt][nt][i] = 0.f;

        #pragma unroll
        for (int ks=0; ks<8; ks++){
            const int k0 = ks*8 + (lane & 3);
            #pragma unroll
            for (int nt=0; nt<8; nt++){
                const int n0 = nt*8 + (lane >> 2);
                const uint32_t bb0 = __float_as_uint(K_[n0*KSS + k0    ]);
                const uint32_t bb1 = __float_as_uint(K_[n0*KSS + k0 + 4]);
                mma8(sc[0][nt], qf[0][ks][0],qf[0][ks][1],qf[0][ks][2],qf[0][ks][3], bb0, bb1);
                mma8(sc[1][nt], qf[1][ks][0],qf[1][ks][1],qf[1][ks][2],qf[1][ks][3], bb0, bb1);
            }
        }

        // scale + causal mask
        const bool diagTile = (kv0 + 63 > q0);
        #pragma unroll
        for (int mt=0; mt<2; mt++){
            #pragma unroll
            for (int nt=0; nt<8; nt++){
                const int c0 = kv0 + nt*8 + 2*(lane & 3);
                #pragma unroll
                for (int i=0; i<4; i++){
                    float s = sc[mt][nt][i] * 0.125f;
                    if (diagTile){
                        const int cc = c0 + (i & 1);
                        const int rr = rg0 + mt*16 + ((i >> 1) * 8);
                        if (cc > rr) s = -1e30f;
                    }
                    sc[mt][nt][i] = s;
                }
            }
        }

        // online softmax per m-tile (2 row-groups each)
        #pragma unroll
        for (int mt=0; mt<2; mt++){
            float m0 = -1e30f, m1 = -1e30f;
            #pragma unroll
            for (int nt=0; nt<8; nt++){
                m0 = fmaxf(m0, fmaxf(sc[mt][nt][0], sc[mt][nt][1]));
                m1 = fmaxf(m1, fmaxf(sc[mt][nt][2], sc[mt][nt][3]));
            }
            m0 = fmaxf(m0, __shfl_xor_sync(0xffffffffu, m0, 1));
            m0 = fmaxf(m0, __shfl_xor_sync(0xffffffffu, m0, 2));
            m1 = fmaxf(m1, __shfl_xor_sync(0xffffffffu, m1, 1));
            m1 = fmaxf(m1, __shfl_xor_sync(0xffffffffu, m1, 2));

            const float mn0 = fmaxf(mi[mt][0], m0);
            const float mn1 = fmaxf(mi[mt][1], m1);
            const float sf0 = __expf(mi[mt][0] - mn0);
            const float sf1 = __expf(mi[mt][1] - mn1);

            float sum0 = 0.f, sum1 = 0.f;
            #pragma unroll
            for (int nt=0; nt<8; nt++){
                sc[mt][nt][0] = __expf(sc[mt][nt][0] - mn0); sum0 += sc[mt][nt][0];
                sc[mt][nt][1] = __expf(sc[mt][nt][1] - mn0); sum0 += sc[mt][nt][1];
                sc[mt][nt][2] = __expf(sc[mt][nt][2] - mn1); sum1 += sc[mt][nt][2];
                sc[mt][nt][3] = __expf(sc[mt][nt][3] - mn1); sum1 += sc[mt][nt][3];
            }
            sum0 += __shfl_xor_sync(0xffffffffu, sum0, 1);
            sum0 += __shfl_xor_sync(0xffffffffu, sum0, 2);
            sum1 += __shfl_xor_sync(0xffffffffu, sum1, 1);
            sum1 += __shfl_xor_sync(0xffffffffu, sum1, 2);

            li[mt][0] = li[mt][0]*sf0 + sum0;
            li[mt][1] = li[mt][1]*sf1 + sum1;
            mi[mt][0] = mn0;  mi[mt][1] = mn1;

            #pragma unroll
            for (int nt=0; nt<8; nt++){
                o[mt][nt][0] *= sf0; o[mt][nt][1] *= sf0;
                o[mt][nt][2] *= sf1; o[mt][nt][3] *= sf1;
            }
        }

        // P -> smem (warp-private rows, tf32 bits)
        #pragma unroll
        for (int mt=0; mt<2; mt++){
            const int rb = rloc + mt*16;
            #pragma unroll
            for (int nt=0; nt<8; nt++){
                const int c0 = nt*8 + 2*(lane & 3);
                sQ[ rb   *QS + c0    ] = __uint_as_float(f2tf(sc[mt][nt][0]));
                sQ[ rb   *QS + c0 + 1] = __uint_as_float(f2tf(sc[mt][nt][1]));
                sQ[(rb+8)*QS + c0    ] = __uint_as_float(f2tf(sc[mt][nt][2]));
                sQ[(rb+8)*QS + c0 + 1] = __uint_as_float(f2tf(sc[mt][nt][3]));
            }
        }
        __syncwarp();

        // O += P @ V (shared V fragments across m-tiles)
        #pragma unroll
        for (int ks=0; ks<8; ks++){
            const int k0 = ks*8 + (lane & 3);
            uint32_t af[2][4];
            #pragma unroll
            for (int mt=0; mt<2; mt++){
                const int rb = rloc + mt*16;
                af[mt][0] = __float_as_uint(sQ[ rb   *QS + k0    ]);
                af[mt][1] = __float_as_uint(sQ[(rb+8)*QS + k0    ]);
                af[mt][2] = __float_as_uint(sQ[ rb   *QS + k0 + 4]);
                af[mt][3] = __float_as_uint(sQ[(rb+8)*QS + k0 + 4]);
            }
            #pragma unroll
            for (int nt=0; nt<8; nt++){
                const int n0 = nt*8 + (lane >> 2);
                const uint32_t bb0 = __float_as_uint(V_[ k0   *VSS + n0]);
                const uint32_t bb1 = __float_as_uint(V_[(k0+4)*VSS + n0]);
                mma8(o[0][nt], af[0][0],af[0][1],af[0][2],af[0][3], bb0, bb1);
                mma8(o[1][nt], af[1][0],af[1][1],af[1][2],af[1][3], bb0, bb1);
            }
        }
    }

    // epilogue: divide by l, store tf32-rounded to [B,L,D]
    const int b = bh >> 4;
    const int h = bh & 15;
    #pragma unroll
    for (int mt=0; mt<2; mt++){
        const float inv0 = 1.f / li[mt][0];
        const float inv1 = 1.f / li[mt][1];
        #pragma unroll
        for (int nt=0; nt<8; nt++){
            const int d0 = nt*8 + 2*(lane & 3);
            #pragma unroll
            for (int i=0; i<4; i++){
                const int rr = rg0 + mt*16 + ((i >> 1) * 8);
                const int dh = d0 + (i & 1);
                const float v = o[mt][nt][i] * ((i >= 2) ? inv1 : inv0);
                Og[((size_t)b*NL + rr)*ND + h*NDH + dh] = tfb(v);
            }
        }
    }
}

// ---------------------------------------------------------------------------
extern "C" void kernel_launch(void* const* d_in, const int* in_sizes, int n_in,
                              void* d_out, int out_size)
{
    (void)in_sizes; (void)n_in; (void)out_size;
    const float* x  = (const float*)d_in[0];
    const float* Wq = (const float*)d_in[1];
    const float* bq = (const float*)d_in[2];
    const float* Wk = (const float*)d_in[3];
    const float* bk = (const float*)d_in[4];
    const float* Wv = (const float*)d_in[5];
    const float* bv = (const float*)d_in[6];
    const float* Wo = (const float*)d_in[7];
    const float* bo = (const float*)d_in[8];
    float* out = (float*)d_out;

    float *gx, *gw, *gq, *gk, *gv, *gatt;
    cudaGetSymbolAddress((void**)&gx,   g_x);
    cudaGetSymbolAddress((void**)&gw,   g_w);
    cudaGetSymbolAddress((void**)&gq,   g_q);
    cudaGetSymbolAddress((void**)&gk,   g_k);
    cudaGetSymbolAddress((void**)&gv,   g_v);
    cudaGetSymbolAddress((void**)&gatt, g_att);

    cudaFuncSetAttribute(gemm_kernel<true>,
        cudaFuncAttributeMaxDynamicSharedMemorySize, GEMM_SMEM);
    cudaFuncSetAttribute(gemm_kernel<false>,
        cudaFuncAttributeMaxDynamicSharedMemorySize, GEMM_SMEM);
    cudaFuncSetAttribute(flash_kernel,
        cudaFuncAttributeMaxDynamicSharedMemorySize, FL_SMEM);

    // 1) pre-round x and weights to tf32
    round_kernel<<<2048, 256>>>(x,  gx, NM*ND/4);
    round_kernel<<<1024, 256>>>(Wq, gw + (size_t)0*ND*ND, ND*ND/4);
    round_kernel<<<1024, 256>>>(Wk, gw + (size_t)1*ND*ND, ND*ND/4);
    round_kernel<<<1024, 256>>>(Wv, gw + (size_t)2*ND*ND, ND*ND/4);
    round_kernel<<<1024, 256>>>(Wo, gw + (size_t)3*ND*ND, ND*ND/4);

    // 2) fused QKV projection
    dim3 gqkv(ND/128, NM/128, 3);   // (8, 64, 3)
    gemm_kernel<true><<<gqkv, 128, GEMM_SMEM>>>(
        gx, gw, bq, bk, bv, gq, gk, gv);

    // 3) flash attention (causal)
    dim3 gf(NL/128, NB*NH);         // (16, 64)
    flash_kernel<<<gf, 128, FL_SMEM>>>(gq, gk, gv, gatt);

    // 4) output projection (weight slab 3)
    dim3 gg(ND/128, NM/128);        // (8, 64)
    gemm_kernel<false><<<gg, 128, GEMM_SMEM>>>(
        gatt, gw, bo, nullptr, nullptr, out, nullptr, nullptr);
}

// round 15
// speedup vs baseline: 1.1158x; 1.0064x over previous
#include <cuda_runtime.h>
#include <cstdint>

#define NB 4
#define NL 2048
#define ND 1024
#define NH 16
#define NDH 64
#define NM (NB*NL)

// Scratch (allocation-free rule: __device__ globals)
static __device__ float g_x[(size_t)NM*ND];     // tf32-rounded x
static __device__ float g_w[(size_t)4*ND*ND];   // tf32-rounded Wq,Wk,Wv,Wo
static __device__ float g_q[(size_t)NM*ND];
static __device__ float g_k[(size_t)NM*ND];
static __device__ float g_v[(size_t)NM*ND];
static __device__ float g_att[(size_t)NM*ND];

__device__ __forceinline__ uint32_t f2tf(float x){
    uint32_t u; asm("cvt.rna.tf32.f32 %0, %1;" : "=r"(u) : "f"(x)); return u;
}
__device__ __forceinline__ float tfb(float x){ return __uint_as_float(f2tf(x)); }
__device__ __forceinline__ float4 tf4(float4 v){
    v.x = tfb(v.x); v.y = tfb(v.y); v.z = tfb(v.z); v.w = tfb(v.w); return v;
}

__device__ __forceinline__ void mma8(float* c,
    uint32_t a0, uint32_t a1, uint32_t a2, uint32_t a3,
    uint32_t b0, uint32_t b1)
{
    asm volatile(
      "mma.sync.aligned.m16n8k8.row.col.f32.tf32.tf32.f32 "
      "{%0,%1,%2,%3},{%4,%5,%6,%7},{%8,%9},{%0,%1,%2,%3};"
      : "+f"(c[0]), "+f"(c[1]), "+f"(c[2]), "+f"(c[3])
      : "r"(a0), "r"(a1), "r"(a2), "r"(a3), "r"(b0), "r"(b1));
}

__device__ __forceinline__ uint32_t smem_u32(const void* p){
    uint32_t a;
    asm("{ .reg .u64 t; cvta.to.shared.u64 t, %1; cvt.u32.u64 %0, t; }" : "=r"(a) : "l"(p));
    return a;
}
__device__ __forceinline__ void cpa16(uint32_t s, const void* g){
    asm volatile("cp.async.cg.shared.global [%0], [%1], 16;" :: "r"(s), "l"(g));
}
#define CP_COMMIT() asm volatile("cp.async.commit_group;" ::: "memory")
#define CP_WAIT0()  asm volatile("cp.async.wait_group 0;" ::: "memory")
#define CP_WAIT1()  asm volatile("cp.async.wait_group 1;" ::: "memory")

// ---------------------------------------------------------------------------
// Fused tf32 pre-round: z=0 -> x, z=1..4 -> Wq,Wk,Wv,Wo  (ONE launch)
// ---------------------------------------------------------------------------
__global__ void round_all_kernel(const float* __restrict__ x,
    const float* __restrict__ Wq, const float* __restrict__ Wk,
    const float* __restrict__ Wv, const float* __restrict__ Wo,
    float* __restrict__ gx, float* __restrict__ gw)
{
    const int z = blockIdx.y;
    const float* src; float* dst; int n4;
    if (z == 0){ src = x; dst = gx; n4 = NM*ND/4; }
    else {
        src = (z == 1) ? Wq : (z == 2) ? Wk : (z == 3) ? Wv : Wo;
        dst = gw + (size_t)(z-1)*ND*ND;
        n4  = ND*ND/4;
    }
    for (int i = blockIdx.x*blockDim.x + threadIdx.x; i < n4; i += gridDim.x*blockDim.x){
        float4 v = reinterpret_cast<const float4*>(src)[i];
        reinterpret_cast<float4*>(dst)[i] = tf4(v);
    }
}

// ---------------------------------------------------------------------------
// GEMM (unchanged from R11): C[8192,1024] = A @ W + bias. Block 128x128x32,
// 4 warps (2x1 of 64x64 warp tiles). Inputs pre-rounded tf32 -> pure cp.async,
// double-buffered. QKV: z selects bias/output, epilogue permutes + re-rounds.
// ---------------------------------------------------------------------------
constexpr int AS_STRIDE = 36;
constexpr int BS_STRIDE = 136;
constexpr int AS_SZ = 128*AS_STRIDE;
constexpr int BS_SZ = 32*BS_STRIDE;
constexpr int GEMM_SMEM = (2*AS_SZ + 2*BS_SZ)*4;   // 71680 B

template<bool QKV>
__global__ void __launch_bounds__(128) gemm_kernel(
    const float* __restrict__ A, const float* __restrict__ Wall,
    const float* __restrict__ bz0, const float* __restrict__ bz1, const float* __restrict__ bz2,
    float* __restrict__ Cz0, float* __restrict__ Cz1, float* __restrict__ Cz2)
{
    extern __shared__ float sm[];
    float* As = sm;
    float* Bs = sm + 2*AS_SZ;
    const uint32_t sbase = smem_u32(sm);
    const uint32_t sbA = sbase;
    const uint32_t sbB = sbase + (uint32_t)(2*AS_SZ*4);

    const int z = QKV ? blockIdx.z : 3;
    const float* W    = Wall + (size_t)z*ND*ND;
    const float* bias = QKV ? ((z == 0) ? bz0 : (z == 1) ? bz1 : bz2) : bz0;
    float* C          = QKV ? ((z == 0) ? Cz0 : (z == 1) ? Cz1 : Cz2) : Cz0;

    const int tid  = threadIdx.x;
    const int lane = tid & 31;
    const int warp = tid >> 5;
    const int wm   = warp >> 1;
    const int wn   = warp & 1;
    const int bm0  = blockIdx.y * 128;
    const int bn0  = blockIdx.x * 128;

    float acc[4][8][4];
    #pragma unroll
    for (int mt=0; mt<4; mt++)
      #pragma unroll
      for (int nt=0; nt<8; nt++)
        #pragma unroll
        for (int i=0; i<4; i++) acc[mt][nt][i] = 0.f;

    const int arow = tid >> 3, ac4 = (tid & 7) * 4;
    const int brow = tid >> 5, bc4 = (tid & 31) * 4;

    auto load_tile = [&](int kt, int buf){
        const uint32_t sa = sbA + (uint32_t)(buf*AS_SZ*4);
        const uint32_t sb = sbB + (uint32_t)(buf*BS_SZ*4);
        #pragma unroll
        for (int p=0; p<8; p++){
            const int row = p*16 + arow;
            cpa16(sa + (uint32_t)((row*AS_STRIDE + ac4)*4),
                  A + (size_t)(bm0 + row)*ND + kt*32 + ac4);
        }
        #pragma unroll
        for (int p=0; p<8; p++){
            const int row = p*4 + brow;
            cpa16(sb + (uint32_t)((row*BS_STRIDE + bc4)*4),
                  W + (size_t)(kt*32 + row)*ND + bn0 + bc4);
        }
    };

    load_tile(0, 0); CP_COMMIT();

    const int NKT = ND/32;
    for (int kt=0; kt<NKT; ++kt){
        const int buf = kt & 1;
        CP_WAIT0();
        __syncthreads();
        if (kt+1 < NKT){ load_tile(kt+1, buf^1); CP_COMMIT(); }

        const float* a_ = As + buf*AS_SZ;
        const float* b_ = Bs + buf*BS_SZ;

        #pragma unroll
        for (int ks=0; ks<4; ks++){
            const int k0 = ks*8 + (lane & 3);
            uint32_t af[4][4];
            #pragma unroll
            for (int mt=0; mt<4; mt++){
                const int r0 = wm*64 + mt*16 + (lane >> 2);
                af[mt][0] = __float_as_uint(a_[ r0   *AS_STRIDE + k0    ]);
                af[mt][1] = __float_as_uint(a_[(r0+8)*AS_STRIDE + k0    ]);
                af[mt][2] = __float_as_uint(a_[ r0   *AS_STRIDE + k0 + 4]);
                af[mt][3] = __float_as_uint(a_[(r0+8)*AS_STRIDE + k0 + 4]);
            }
            #pragma unroll
            for (int nt=0; nt<8; nt++){
                const int n0 = wn*64 + nt*8 + (lane >> 2);
                const uint32_t bb0 = __float_as_uint(b_[ k0   *BS_STRIDE + n0]);
                const uint32_t bb1 = __float_as_uint(b_[(k0+4)*BS_STRIDE + n0]);
                #pragma unroll
                for (int mt=0; mt<4; mt++)
                    mma8(acc[mt][nt], af[mt][0],af[mt][1],af[mt][2],af[mt][3], bb0, bb1);
            }
        }
    }

    #pragma unroll
    for (int mt=0; mt<4; mt++){
        const int rbase = bm0 + wm*64 + mt*16 + (lane >> 2);
        #pragma unroll
        for (int nt=0; nt<8; nt++){
            const int cbase = bn0 + wn*64 + nt*8 + 2*(lane & 3);
            #pragma unroll
            for (int i=0; i<4; i++){
                const int r = rbase + (i>>1)*8;
                const int c = cbase + (i&1);
                const float v = acc[mt][nt][i] + bias[c];
                if (QKV){
                    const size_t idx = (((size_t)(r >> 11)*NH + (c >> 6))*NL + (r & (NL-1)))*NDH + (c & 63);
                    C[idx] = tfb(v);
                } else {
                    C[(size_t)r*ND + c] = v;
                }
            }
        }
    }
}

// ---------------------------------------------------------------------------
// FlashAttention-2, causal. BM=64 q rows/CTA, BN=64 keys/step, 4 warps x 16
// rows, 128 threads, __launch_bounds__(128,3) -> 12 warps/SM (3 CTAs).
// K double-buffered; V single-buffered (load hides behind S+softmax via
// wait_group accounting). Q region reused as P. Inputs pre-rounded tf32.
// ---------------------------------------------------------------------------
constexpr int FQS = 68;                         // sQ / sP stride
constexpr int FKS = 68;
constexpr int FVS = 72;
constexpr int FK_OFF = 64*FQS;                  // after sQ
constexpr int FV_OFF = FK_OFF + 2*64*FKS;       // after 2 K buffers
constexpr int FL_SMEM = (FV_OFF + 64*FVS)*4;    // 70656 B -> 3 CTAs/SM

__global__ void __launch_bounds__(128, 3) flash_kernel(
    const float* __restrict__ Qg, const float* __restrict__ Kg,
    const float* __restrict__ Vg, float* __restrict__ Og)
{
    extern __shared__ float sm[];
    float* sQ = sm;                                        // [64][68], reused as P
    float* sKb[2] = { sm + FK_OFF, sm + FK_OFF + 64*FKS };
    float* sV = sm + FV_OFF;                               // [64][72]
    const uint32_t sbase = smem_u32(sm);

    const int tid  = threadIdx.x;
    const int lane = tid & 31;
    const int warp = tid >> 5;          // 0..3
    const int bh   = blockIdx.y;
    const int q0   = blockIdx.x * 64;

    const float* Qb = Qg + (size_t)bh*NL*NDH;
    const float* Kb = Kg + (size_t)bh*NL*NDH;
    const float* Vb = Vg + (size_t)bh*NL*NDH;

    const int r_ = tid >> 4;            // 0..7
    const int c4 = (tid & 15) * 4;      // 0..60

    // Q tile [64,64] via cp.async (already tf32)
    #pragma unroll
    for (int p=0; p<8; p++){
        const int row = p*8 + r_;
        cpa16(sbase + (uint32_t)((row*FQS + c4)*4), Qb + (size_t)(q0 + row)*NDH + c4);
    }
    CP_COMMIT();

    auto load_k = [&](int t, int buf){
        const uint32_t kb = sbase + (uint32_t)((FK_OFF + buf*64*FKS)*4);
        #pragma unroll
        for (int p=0; p<8; p++){
            const int row = p*8 + r_;
            cpa16(kb + (uint32_t)((row*FKS + c4)*4), Kb + (size_t)(t*64 + row)*NDH + c4);
        }
    };
    auto load_v = [&](int t){
        const uint32_t vb = sbase + (uint32_t)(FV_OFF*4);
        #pragma unroll
        for (int p=0; p<8; p++){
            const int row = p*8 + r_;
            cpa16(vb + (uint32_t)((row*FVS + c4)*4), Vb + (size_t)(t*64 + row)*NDH + c4);
        }
    };

    CP_WAIT0();                 // Q arrived
    __syncthreads();

    // Q fragments (warp-private 16 rows)
    uint32_t qf[8][4];
    const int rloc = warp*16 + (lane >> 2);
    #pragma unroll
    for (int ks=0; ks<8; ks++){
        const int k0 = ks*8 + (lane & 3);
        qf[ks][0] = __float_as_uint(sQ[ rloc   *FQS + k0    ]);
        qf[ks][1] = __float_as_uint(sQ[(rloc+8)*FQS + k0    ]);
        qf[ks][2] = __float_as_uint(sQ[ rloc   *FQS + k0 + 4]);
        qf[ks][3] = __float_as_uint(sQ[(rloc+8)*FQS + k0 + 4]);
    }

    load_k(0, 0); CP_COMMIT();

    float o[8][4];
    #pragma unroll
    for (int nt=0; nt<8; nt++)
      #pragma unroll
      for (int i=0; i<4; i++) o[nt][i] = 0.f;

    float mi0 = -1e30f, mi1 = -1e30f, li0 = 0.f, li1 = 0.f;
    const int rg0 = q0 + rloc;
    const int ntile = q0/64 + 1;        // causal: keys up to q0+63

    for (int t=0; t<ntile; ++t){
        const int buf = t & 1;
        CP_WAIT0();                     // K(t) arrived (and all older groups drained)
        __syncthreads();                // all warps past P@V(t-1): sV/sK(buf^1) reads done

        load_v(t); CP_COMMIT();         // V(t) -> single buffer; hides behind S+softmax

        const float* K_ = sKb[buf];

        // S = Q @ K^T
        float sc[8][4];
        #pragma unroll
        for (int nt=0; nt<8; nt++)
          #pragma unroll
          for (int i=0; i<4; i++) sc[nt][i] = 0.f;

        #pragma unroll
        for (int ks=0; ks<8; ks++){
            const int k0 = ks*8 + (lane & 3);
            #pragma unroll
            for (int nt=0; nt<8; nt++){
                const int n0 = nt*8 + (lane >> 2);
                const uint32_t bb0 = __float_as_uint(K_[n0*FKS + k0    ]);
                const uint32_t bb1 = __float_as_uint(K_[n0*FKS + k0 + 4]);
                mma8(sc[nt], qf[ks][0],qf[ks][1],qf[ks][2],qf[ks][3], bb0, bb1);
            }
        }

        const bool hasNext = (t+1 < ntile);
        if (hasNext){ load_k(t+1, buf^1); CP_COMMIT(); }   // hides behind softmax+PV

        // scale + causal mask (only last tile touches the diagonal)
        const int kv0 = t*64;
        const bool diagTile = (t == ntile-1);
        #pragma unroll
        for (int nt=0; nt<8; nt++){
            const int c0 = kv0 + nt*8 + 2*(lane & 3);
            #pragma unroll
            for (int i=0; i<4; i++){
                float s = sc[nt][i] * 0.125f;
                if (diagTile){
                    const int cc = c0 + (i & 1);
                    const int rr = rg0 + ((i >> 1) * 8);
                    if (cc > rr) s = -1e30f;
                }
                sc[nt][i] = s;
            }
        }

        // online softmax (2 row-groups; quad lanes share rows)
        float mt0 = -1e30f, mt1 = -1e30f;
        #pragma unroll
        for (int nt=0; nt<8; nt++){
            mt0 = fmaxf(mt0, fmaxf(sc[nt][0], sc[nt][1]));
            mt1 = fmaxf(mt1, fmaxf(sc[nt][2], sc[nt][3]));
        }
        mt0 = fmaxf(mt0, __shfl_xor_sync(0xffffffffu, mt0, 1));
        mt0 = fmaxf(mt0, __shfl_xor_sync(0xffffffffu, mt0, 2));
        mt1 = fmaxf(mt1, __shfl_xor_sync(0xffffffffu, mt1, 1));
        mt1 = fmaxf(mt1, __shfl_xor_sync(0xffffffffu, mt1, 2));

        const float mn0 = fmaxf(mi0, mt0);
        const float mn1 = fmaxf(mi1, mt1);
        const float sf0 = __expf(mi0 - mn0);
        const float sf1 = __expf(mi1 - mn1);

        float sum0 = 0.f, sum1 = 0.f;
        #pragma unroll
        for (int nt=0; nt<8; nt++){
            sc[nt][0] = __expf(sc[nt][0] - mn0); sum0 += sc[nt][0];
            sc[nt][1] = __expf(sc[nt][1] - mn0); sum0 += sc[nt][1];
            sc[nt][2] = __expf(sc[nt][2] - mn1); sum1 += sc[nt][2];
            sc[nt][3] = __expf(sc[nt][3] - mn1); sum1 += sc[nt][3];
        }
        sum0 += __shfl_xor_sync(0xffffffffu, sum0, 1);
        sum0 += __shfl_xor_sync(0xffffffffu, sum0, 2);
        sum1 += __shfl_xor_sync(0xffffffffu, sum1, 1);
        sum1 += __shfl_xor_sync(0xffffffffu, sum1, 2);

        li0 = li0*sf0 + sum0;  li1 = li1*sf1 + sum1;
        mi0 = mn0;             mi1 = mn1;

        #pragma unroll
        for (int nt=0; nt<8; nt++){
            o[nt][0] *= sf0; o[nt][1] *= sf0;
            o[nt][2] *= sf1; o[nt][3] *= sf1;
        }

        // V(t) must be in before P@V; K(t+1) may remain outstanding
        if (hasNext) { CP_WAIT1(); } else { CP_WAIT0(); }
        __syncthreads();

        // P -> smem (warp-private rows, tf32 bits)
        #pragma unroll
        for (int nt=0; nt<8; nt++){
            const int c0 = nt*8 + 2*(lane & 3);
            sQ[ rloc   *FQS + c0    ] = __uint_as_float(f2tf(sc[nt][0]));
            sQ[ rloc   *FQS + c0 + 1] = __uint_as_float(f2tf(sc[nt][1]));
            sQ[(rloc+8)*FQS + c0    ] = __uint_as_float(f2tf(sc[nt][2]));
            sQ[(rloc+8)*FQS + c0 + 1] = __uint_as_float(f2tf(sc[nt][3]));
        }
        __syncwarp();

        // O += P @ V
        #pragma unroll
        for (int ks=0; ks<8; ks++){
            const int k0 = ks*8 + (lane & 3);
            const uint32_t a0 = __float_as_uint(sQ[ rloc   *FQS + k0    ]);
            const uint32_t a1 = __float_as_uint(sQ[(rloc+8)*FQS + k0    ]);
            const uint32_t a2 = __float_as_uint(sQ[ rloc   *FQS + k0 + 4]);
            const uint32_t a3 = __float_as_uint(sQ[(rloc+8)*FQS + k0 + 4]);
            #pragma unroll
            for (int nt=0; nt<8; nt++){
                const int n0 = nt*8 + (lane >> 2);
                const uint32_t bb0 = __float_as_uint(sV[ k0   *FVS + n0]);
                const uint32_t bb1 = __float_as_uint(sV[(k0+4)*FVS + n0]);
                mma8(o[nt], a0, a1, a2, a3, bb0, bb1);
            }
        }
    }

    // epilogue: divide by l, store tf32-rounded to [B,L,D]
    const float inv0 = 1.f / li0;
    const float inv1 = 1.f / li1;
    const int b = bh >> 4;
    const int h = bh & 15;
    #pragma unroll
    for (int nt=0; nt<8; nt++){
        const int d0 = nt*8 + 2*(lane & 3);
        #pragma unroll
        for (int i=0; i<4; i++){
            const int rr = rg0 + ((i >> 1) * 8);
            const int dh = d0 + (i & 1);
            const float v = o[nt][i] * ((i >= 2) ? inv1 : inv0);
            Og[((size_t)b*NL + rr)*ND + h*NDH + dh] = tfb(v);
        }
    }
}

// ---------------------------------------------------------------------------
extern "C" void kernel_launch(void* const* d_in, const int* in_sizes, int n_in,
                              void* d_out, int out_size)
{
    (void)in_sizes; (void)n_in; (void)out_size;
    const float* x  = (const float*)d_in[0];
    const float* Wq = (const float*)d_in[1];
    const float* bq = (const float*)d_in[2];
    const float* Wk = (const float*)d_in[3];
    const float* bk = (const float*)d_in[4];
    const float* Wv = (const float*)d_in[5];
    const float* bv = (const float*)d_in[6];
    const float* Wo = (const float*)d_in[7];
    const float* bo = (const float*)d_in[8];
    float* out = (float*)d_out;

    float *gx, *gw, *gq, *gk, *gv, *gatt;
    cudaGetSymbolAddress((void**)&gx,   g_x);
    cudaGetSymbolAddress((void**)&gw,   g_w);
    cudaGetSymbolAddress((void**)&gq,   g_q);
    cudaGetSymbolAddress((void**)&gk,   g_k);
    cudaGetSymbolAddress((void**)&gv,   g_v);
    cudaGetSymbolAddress((void**)&gatt, g_att);

    cudaFuncSetAttribute(gemm_kernel<true>,
        cudaFuncAttributeMaxDynamicSharedMemorySize, GEMM_SMEM);
    cudaFuncSetAttribute(gemm_kernel<false>,
        cudaFuncAttributeMaxDynamicSharedMemorySize, GEMM_SMEM);
    cudaFuncSetAttribute(flash_kernel,
        cudaFuncAttributeMaxDynamicSharedMemorySize, FL_SMEM);

    // 1) fused pre-round of x + all weights (one launch)
    dim3 rg(1024, 5);
    round_all_kernel<<<rg, 256>>>(x, Wq, Wk, Wv, Wo, gx, gw);

    // 2) fused QKV projection
    dim3 gqkv(ND/128, NM/128, 3);   // (8, 64, 3)
    gemm_kernel<true><<<gqkv, 128, GEMM_SMEM>>>(
        gx, gw, bq, bk, bv, gq, gk, gv);

    // 3) flash attention (causal), BM=64, 3 CTAs/SM
    dim3 gf(NL/64, NB*NH);          // (32, 64)
    flash_kernel<<<gf, 128, FL_SMEM>>>(gq, gk, gv, gatt);

    // 4) output projection (weight slab 3)
    dim3 gg(ND/128, NM/128);        // (8, 64)
    gemm_kernel<false><<<gg, 128, GEMM_SMEM>>>(
        gatt, gw, bo, nullptr, nullptr, out, nullptr, nullptr);
}